// round 7
// baseline (speedup 1.0000x reference)
#include <cuda_runtime.h>
#include <math.h>
#include <stdint.h>

#define K_CL 1024
#define DM   256
#define NPX  65536
#define NISO 12
#define RBLK 304
#define CHUNK 216

typedef unsigned long long u64;

__device__ __forceinline__ u64 pack2(float lo, float hi) {
    u64 r;
    asm("mov.b64 %0, {%1, %2};" : "=l"(r)
        : "r"(__float_as_uint(lo)), "r"(__float_as_uint(hi)));
    return r;
}
__device__ __forceinline__ void unpack2(u64 v, float& lo, float& hi) {
    unsigned a, b;
    asm("mov.b64 {%0, %1}, %2;" : "=r"(a), "=r"(b) : "l"(v));
    lo = __uint_as_float(a); hi = __uint_as_float(b);
}
__device__ __forceinline__ u64 fma2(u64 a, u64 b, u64 c) {
    u64 d;
    asm("fma.rn.f32x2 %0, %1, %2, %3;" : "=l"(d) : "l"(a), "l"(b), "l"(c));
    return d;
}

// ---------------- device scratch ----------------
__device__ float g_part[2 * RBLK * 15 * K_CL];
__device__ float g_S[2 * 15 * K_CL];
__device__ float g_GU[K_CL * 32];
__device__ float g_GV[K_CL * 32];
__device__ float g_HA[K_CL * 32];
__device__ float g_HB[K_CL * 32];
__device__ float g_QC[K_CL * 2];
__device__ float g_KC[K_CL * 2];
__device__ float g_R[K_CL * K_CL];
__device__ float g_L[K_CL * K_CL];
__device__ float g_AO[K_CL * DM];
__device__ float g_X[K_CL * DM];
__device__ float g_F1[K_CL * 4 * DM];
__device__ float g_F2[K_CL * DM];

// ---------------- kernel 1: fused A^T reductions (sequential, HBM bound) ----------
__launch_bounds__(256)
__global__ void reduce_k(const float* __restrict__ qA, const float* __restrict__ kA,
                         const float* __restrict__ qco, const float* __restrict__ kco,
                         const int* __restrict__ qiso, const int* __restrict__ kiso)
{
    __shared__ float4 sIso[NISO * 256];   // 48KB
    const int tid = threadIdx.x;
    const int bx  = blockIdx.x;
    const int mat = blockIdx.y;
    const float* __restrict__ A   = mat ? kA   : qA;
    const float2* __restrict__ co2 = (const float2*)(mat ? kco : qco);
    const int*   __restrict__ iso = mat ? kiso : qiso;

    for (int i = tid; i < NISO * 256; i += 256) sIso[i] = make_float4(0.f, 0.f, 0.f, 0.f);
    __syncthreads();

    float4 sx = make_float4(0,0,0,0), sy = sx, ss = sx;

    const int base = bx * CHUNK;
    const int end  = (base + CHUNK < NPX) ? base + CHUNK : NPX;
    const float4* __restrict__ A4 = (const float4*)A;

    for (int r = base; r < end; r += 4) {
        float4 a0 = A4[(size_t)(r+0) * 256 + tid];
        float4 a1 = A4[(size_t)(r+1) * 256 + tid];
        float4 a2 = A4[(size_t)(r+2) * 256 + tid];
        float4 a3 = A4[(size_t)(r+3) * 256 + tid];
        float2 c0 = __ldg(co2 + r+0), c1 = __ldg(co2 + r+1);
        float2 c2 = __ldg(co2 + r+2), c3 = __ldg(co2 + r+3);
        int i0 = __ldg(iso + r+0) - 1, i1 = __ldg(iso + r+1) - 1;
        int i2 = __ldg(iso + r+2) - 1, i3 = __ldg(iso + r+3) - 1;

        #define ACC(a, c, ic) do { \
            sx.x = fmaf(a.x, c.x, sx.x); sx.y = fmaf(a.y, c.x, sx.y); \
            sx.z = fmaf(a.z, c.x, sx.z); sx.w = fmaf(a.w, c.x, sx.w); \
            sy.x = fmaf(a.x, c.y, sy.x); sy.y = fmaf(a.y, c.y, sy.y); \
            sy.z = fmaf(a.z, c.y, sy.z); sy.w = fmaf(a.w, c.y, sy.w); \
            ss.x += a.x; ss.y += a.y; ss.z += a.z; ss.w += a.w; \
            float4 t = sIso[(ic) * 256 + tid]; \
            t.x += a.x; t.y += a.y; t.z += a.z; t.w += a.w; \
            sIso[(ic) * 256 + tid] = t; } while (0)

        ACC(a0, c0, i0); ACC(a1, c1, i1); ACC(a2, c2, i2); ACC(a3, c3, i3);
        #undef ACC
    }

    float4* P4 = (float4*)(g_part + (size_t)(mat * RBLK + bx) * 15 * K_CL);
    P4[0 * 256 + tid] = sx;
    P4[1 * 256 + tid] = sy;
    P4[2 * 256 + tid] = ss;
    #pragma unroll
    for (int c = 0; c < NISO; c++)
        P4[(3 + c) * 256 + tid] = sIso[c * 256 + tid];
}

// ---------------- kernel 2: reduce partials ----------------
__global__ void reduce2_k()
{
    int idx = blockIdx.x * 256 + threadIdx.x;
    int mat = idx / (15 * K_CL);
    int rem = idx % (15 * K_CL);
    const float* P = g_part + (size_t)mat * RBLK * 15 * K_CL + rem;
    float s = 0.f;
    #pragma unroll 8
    for (int b = 0; b < RBLK; b++) s += P[(size_t)b * 15 * K_CL];
    g_S[idx] = s;
}

// ---------------- kernel 3: per-cluster features ----------------
__global__ void cfeat_k(const float* __restrict__ sensor,
                        const float* __restrict__ g1w, const float* __restrict__ g1b,
                        const float* __restrict__ h1w, const float* __restrict__ h1b)
{
    int k = blockIdx.x * 256 + threadIdx.x;
    float dq[NISO], dkp[NISO];

    float sq  = g_S[(0*15 + 2)*K_CL + k];
    float qcx = g_S[(0*15 + 0)*K_CL + k] / (sq + 1e-6f);
    float qcy = g_S[(0*15 + 1)*K_CL + k] / (sq + 1e-6f);
    float sk  = g_S[(1*15 + 2)*K_CL + k];
    float kcx = g_S[(1*15 + 0)*K_CL + k] / (sk + 1e-6f);
    float kcy = g_S[(1*15 + 1)*K_CL + k] / (sk + 1e-6f);

    float sum0 = 0.f, sum1 = 0.f;
    #pragma unroll
    for (int c = 0; c < NISO; c++) {
        dq[c]  = g_S[(0*15 + 3 + c)*K_CL + k];  sum0 += dq[c];
        dkp[c] = g_S[(1*15 + 3 + c)*K_CL + k];  sum1 += dkp[c];
    }
    #pragma unroll
    for (int c = 0; c < NISO; c++) { dq[c] /= sum0; dkp[c] /= sum1; }

    float sxn = sensor[0], syn = sensor[1];
    float nks  = sqrtf((qcx - sxn)*(qcx - sxn) + (qcy - syn)*(qcy - syn));
    float nkps = sqrtf((kcx - sxn)*(kcx - sxn) + (kcy - syn)*(kcy - syn));

    g_QC[2*k] = qcx; g_QC[2*k+1] = qcy;
    g_KC[2*k] = kcx; g_KC[2*k+1] = kcy;

    for (int o = 0; o < 32; o++) {
        float u = g1b[o], v = 0.f;
        #pragma unroll
        for (int c = 0; c < NISO; c++) {
            u = fmaf(dq[c],  g1w[c*32 + o],          u);
            v = fmaf(dkp[c], g1w[(NISO + c)*32 + o], v);
        }
        g_GU[k*32 + o] = u;
        g_GV[k*32 + o] = v;
        g_HA[k*32 + o] = fmaf(nks, h1w[32 + o], h1b[o]);
        g_HB[k*32 + o] = nkps * h1w[64 + o];
    }
}

// ---------------- kernel 4: R factor ----------------
__launch_bounds__(256)
__global__ void rfactor_k(const float* __restrict__ g2w, const float* __restrict__ g2b,
                          const float* __restrict__ h2w, const float* __restrict__ h2b,
                          const float* __restrict__ h1w)
{
    __shared__ float sGU[32][68], sGV[32][68], sHA[32][68], sHB[32][68];
    __shared__ float sW[96];
    __shared__ float sQC[64][2], sKC[64][2];

    const int tid = threadIdx.x;
    const int ib = blockIdx.y * 64, jb = blockIdx.x * 64;

    #pragma unroll
    for (int p = 0; p < 2; p++) {
        int idx = tid + p * 256;
        int row = idx >> 3, c0 = (idx & 7) * 4;
        float4 u = *(const float4*)&g_GU[(ib + row)*32 + c0];
        sGU[c0][row] = u.x; sGU[c0+1][row] = u.y; sGU[c0+2][row] = u.z; sGU[c0+3][row] = u.w;
        float4 v = *(const float4*)&g_GV[(jb + row)*32 + c0];
        sGV[c0][row] = v.x; sGV[c0+1][row] = v.y; sGV[c0+2][row] = v.z; sGV[c0+3][row] = v.w;
        float4 a = *(const float4*)&g_HA[(ib + row)*32 + c0];
        sHA[c0][row] = a.x; sHA[c0+1][row] = a.y; sHA[c0+2][row] = a.z; sHA[c0+3][row] = a.w;
        float4 b = *(const float4*)&g_HB[(jb + row)*32 + c0];
        sHB[c0][row] = b.x; sHB[c0+1][row] = b.y; sHB[c0+2][row] = b.z; sHB[c0+3][row] = b.w;
    }
    if (tid < 32)       sW[tid] = g2w[tid];
    else if (tid < 64)  sW[tid] = h2w[tid - 32];
    else if (tid < 96)  sW[tid] = h1w[tid - 64];
    if (tid < 128)      sQC[tid >> 1][tid & 1] = g_QC[(ib + (tid >> 1))*2 + (tid & 1)];
    else                { int t = tid - 128; sKC[t >> 1][t & 1] = g_KC[(jb + (t >> 1))*2 + (t & 1)]; }
    __syncthreads();

    const int ty = tid >> 4, tx = tid & 15;
    float nkk[4][4];
    #pragma unroll
    for (int m = 0; m < 4; m++) {
        float qx = sQC[ty*4 + m][0], qy = sQC[ty*4 + m][1];
        #pragma unroll
        for (int n = 0; n < 4; n++) {
            float dx = qx - sKC[tx*4 + n][0], dy = qy - sKC[tx*4 + n][1];
            nkk[m][n] = sqrtf(dx*dx + dy*dy);
        }
    }

    float gacc[4][4], hacc[4][4];
    #pragma unroll
    for (int m = 0; m < 4; m++)
        #pragma unroll
        for (int n = 0; n < 4; n++) { gacc[m][n] = 0.f; hacc[m][n] = 0.f; }

    #pragma unroll 4
    for (int c = 0; c < 32; c++) {
        float gw = sW[c], hw = sW[32 + c], w1c = sW[64 + c];
        float4 au = *(const float4*)&sGU[c][ty*4];
        float4 aa = *(const float4*)&sHA[c][ty*4];
        float4 bv = *(const float4*)&sGV[c][tx*4];
        float4 bb = *(const float4*)&sHB[c][tx*4];
        const float* aup = &au.x; const float* aap = &aa.x;
        const float* bvp = &bv.x; const float* bbp = &bb.x;
        #pragma unroll
        for (int m = 0; m < 4; m++)
            #pragma unroll
            for (int n = 0; n < 4; n++) {
                float g = fmaxf(aup[m] + bvp[n], 0.f);
                gacc[m][n] = fmaf(g, gw, gacc[m][n]);
                float h = fmaxf(fmaf(nkk[m][n], w1c, aap[m] + bbp[n]), 0.f);
                hacc[m][n] = fmaf(h, hw, hacc[m][n]);
            }
    }

    const float g2b0 = g2b[0], h2b0 = h2b[0];
    #pragma unroll
    for (int m = 0; m < 4; m++) {
        float4 o;
        float* op = &o.x;
        #pragma unroll
        for (int n = 0; n < 4; n++)
            op[n] = fmaxf(gacc[m][n] + g2b0, 0.f) * fmaxf(hacc[m][n] + h2b0, 0.f);
        *(float4*)&g_R[(size_t)(ib + ty*4 + m) * K_CL + jb + tx*4] = o;
    }
}

// ---------------- zero-pack pipelined f32x2 GEMM, conflict-free smem ----------------
// Bs holds duplicated (b,b) u64 pairs in layout [kk][n*16 + tx]:
//   compute-load bank = 2*tx  -> conflict-free (upper half-warp broadcasts).
// a-pairs (adjacent rows) read as aligned LDS.64 broadcast from As.
// Inner loop is pure fma.rn.f32x2.
// MODE 0: store; 1: *scale*ext[i*N+j]; 2: relu(+ext[j]); 3: +ext[j].
template<int TM, int MODE, bool BT>
__launch_bounds__(256)
__global__ void gemm_k4(const float* __restrict__ A, const float* __restrict__ B,
                        float* __restrict__ C, int M, int N, int Kd,
                        const float* __restrict__ ext, float scale)
{
    constexpr int TN = 64;
    constexpr int RM = TM / 16;     // rows per thread (8 or 2)
    constexpr int MP = RM / 2;      // row-pairs per thread
    constexpr int NA = (TM * 4 + 255) / 256;
    __shared__ float As[2][16][TM];
    __shared__ u64   Bs[2][16][TN];   // [kk][n*16 + tx]

    const int tid = threadIdx.x;
    const int tx = tid & 15, ty = tid >> 4;
    const int row0 = blockIdx.y * TM, col0 = blockIdx.x * TN;

    float4 ra[NA];
    float4 rb;

    // B fill mapping (computed once)
    //  BT:    thread -> column j = (tid&15)*4 + ((tid>>4)&3), k-quad kk4 = (tid>>6)*4
    //  nonBT: thread -> k row kk = tid>>4, column quad j0 = (tid&15)*4
    const int bt_j   = (tid & 15) * 4 + ((tid >> 4) & 3);
    const int bt_kk4 = (tid >> 6) * 4;
    const int nb_kk  = tid >> 4;
    const int nb_t   = tid & 15;

    auto ldTile = [&](int k0) {
        #pragma unroll
        for (int i = 0; i < NA; i++) {
            int idx = tid + i * 256;
            if ((TM * 4) % 256 == 0 || idx < TM * 4) {
                int lr = idx >> 2, lc = (idx & 3) * 4;
                ra[i] = *(const float4*)(A + (size_t)(row0 + lr) * Kd + k0 + lc);
            }
        }
        if (BT) {
            rb = *(const float4*)(B + (size_t)(col0 + bt_j) * Kd + k0 + bt_kk4);
        } else {
            rb = *(const float4*)(B + (size_t)(k0 + nb_kk) * N + col0 + nb_t * 4);
        }
    };
    auto stTile = [&](int buf) {
        #pragma unroll
        for (int i = 0; i < NA; i++) {
            int idx = tid + i * 256;
            if ((TM * 4) % 256 == 0 || idx < TM * 4) {
                int lr = idx >> 2, lc = (idx & 3) * 4;
                As[buf][lc+0][lr] = ra[i].x; As[buf][lc+1][lr] = ra[i].y;
                As[buf][lc+2][lr] = ra[i].z; As[buf][lc+3][lr] = ra[i].w;
            }
        }
        if (BT) {
            // rb.x..rb.w are k-consecutive at fixed column bt_j
            int slot = (bt_j & 3) * 16 + (bt_j >> 2);
            Bs[buf][bt_kk4 + 0][slot] = pack2(rb.x, rb.x);
            Bs[buf][bt_kk4 + 1][slot] = pack2(rb.y, rb.y);
            Bs[buf][bt_kk4 + 2][slot] = pack2(rb.z, rb.z);
            Bs[buf][bt_kk4 + 3][slot] = pack2(rb.w, rb.w);
        } else {
            // rb.x..rb.w are column-consecutive at fixed k row nb_kk
            Bs[buf][nb_kk][0 * 16 + nb_t] = pack2(rb.x, rb.x);
            Bs[buf][nb_kk][1 * 16 + nb_t] = pack2(rb.y, rb.y);
            Bs[buf][nb_kk][2 * 16 + nb_t] = pack2(rb.z, rb.z);
            Bs[buf][nb_kk][3 * 16 + nb_t] = pack2(rb.w, rb.w);
        }
    };

    u64 acc[MP][4];
    #pragma unroll
    for (int p = 0; p < MP; p++)
        #pragma unroll
        for (int n = 0; n < 4; n++) acc[p][n] = 0ULL;

    const int nt = Kd >> 4;
    ldTile(0);
    stTile(0);
    __syncthreads();

    for (int t = 0; t < nt; t++) {
        const int cur = t & 1;
        if (t + 1 < nt) ldTile((t + 1) << 4);

        #pragma unroll
        for (int kk = 0; kk < 16; kk++) {
            u64 a[MP];
            #pragma unroll
            for (int p = 0; p < MP; p++)
                a[p] = *(const u64*)&As[cur][kk][ty * RM + 2 * p];
            u64 b0 = Bs[cur][kk][0 * 16 + tx];
            u64 b1 = Bs[cur][kk][1 * 16 + tx];
            u64 b2 = Bs[cur][kk][2 * 16 + tx];
            u64 b3 = Bs[cur][kk][3 * 16 + tx];
            #pragma unroll
            for (int p = 0; p < MP; p++) {
                acc[p][0] = fma2(a[p], b0, acc[p][0]);
                acc[p][1] = fma2(a[p], b1, acc[p][1]);
                acc[p][2] = fma2(a[p], b2, acc[p][2]);
                acc[p][3] = fma2(a[p], b3, acc[p][3]);
            }
        }

        if (t + 1 < nt) {
            stTile((t + 1) & 1);
            __syncthreads();
        }
    }

    const int j0 = col0 + tx * 4;
    #pragma unroll
    for (int p = 0; p < MP; p++) {
        float lo[4], hi[4];
        #pragma unroll
        for (int n = 0; n < 4; n++) unpack2(acc[p][n], lo[n], hi[n]);
        int i0 = row0 + ty * RM + 2 * p;
        #pragma unroll
        for (int h = 0; h < 2; h++) {
            int i = i0 + h;
            float v0 = h ? hi[0] : lo[0], v1 = h ? hi[1] : lo[1];
            float v2 = h ? hi[2] : lo[2], v3 = h ? hi[3] : lo[3];
            if (MODE == 1) {
                float4 r = *(const float4*)(ext + (size_t)i * N + j0);
                v0 = v0 * scale * r.x; v1 = v1 * scale * r.y;
                v2 = v2 * scale * r.z; v3 = v3 * scale * r.w;
            } else if (MODE == 2) {
                v0 = fmaxf(v0 + ext[j0+0], 0.f); v1 = fmaxf(v1 + ext[j0+1], 0.f);
                v2 = fmaxf(v2 + ext[j0+2], 0.f); v3 = fmaxf(v3 + ext[j0+3], 0.f);
            } else if (MODE == 3) {
                v0 += ext[j0+0]; v1 += ext[j0+1]; v2 += ext[j0+2]; v3 += ext[j0+3];
            }
            float4 o; o.x = v0; o.y = v1; o.z = v2; o.w = v3;
            *(float4*)(C + (size_t)i * N + j0) = o;
        }
    }
}

// ---------------- softmax ----------------
__global__ void softmax_k(float* __restrict__ X)
{
    const int row = blockIdx.x, tid = threadIdx.x;
    __shared__ float red[256];
    float v[4];
    float m = -3.4e38f;
    #pragma unroll
    for (int j = 0; j < 4; j++) { v[j] = X[(size_t)row * K_CL + tid + j * 256]; m = fmaxf(m, v[j]); }
    red[tid] = m; __syncthreads();
    #pragma unroll
    for (int s = 128; s > 0; s >>= 1) { if (tid < s) red[tid] = fmaxf(red[tid], red[tid + s]); __syncthreads(); }
    m = red[0]; __syncthreads();
    float sum = 0.f;
    #pragma unroll
    for (int j = 0; j < 4; j++) { v[j] = __expf(v[j] - m); sum += v[j]; }
    red[tid] = sum; __syncthreads();
    #pragma unroll
    for (int s = 128; s > 0; s >>= 1) { if (tid < s) red[tid] += red[tid + s]; __syncthreads(); }
    float inv = 1.f / red[0];
    #pragma unroll
    for (int j = 0; j < 4; j++) X[(size_t)row * K_CL + tid + j * 256] = v[j] * inv;
}

// ---------------- residual add + LayerNorm ----------------
__global__ void add_ln_k(const float* __restrict__ a, const float* __restrict__ b,
                         const float* __restrict__ g, const float* __restrict__ be,
                         float* __restrict__ out)
{
    const int row = blockIdx.x, tid = threadIdx.x;
    __shared__ float red[256];
    float x = a[row * DM + tid] + b[row * DM + tid];
    red[tid] = x; __syncthreads();
    #pragma unroll
    for (int s = 128; s > 0; s >>= 1) { if (tid < s) red[tid] += red[tid + s]; __syncthreads(); }
    float mean = red[0] * (1.f / DM); __syncthreads();
    float d = x - mean;
    red[tid] = d * d; __syncthreads();
    #pragma unroll
    for (int s = 128; s > 0; s >>= 1) { if (tid < s) red[tid] += red[tid + s]; __syncthreads(); }
    float var = red[0] * (1.f / DM);
    out[row * DM + tid] = d * rsqrtf(var + 1e-6f) * g[tid] + be[tid];
}

// ---------------- launch ----------------
extern "C" void kernel_launch(void* const* d_in, const int* in_sizes, int n_in,
                              void* d_out, int out_size)
{
    const float* sensor = (const float*)d_in[0];
    const float* query  = (const float*)d_in[1];
    const float* keyemb = (const float*)d_in[2];
    const float* qA     = (const float*)d_in[3];
    const float* kA     = (const float*)d_in[4];
    const float* qco    = (const float*)d_in[5];
    const float* kco    = (const float*)d_in[6];
    const int*   qiso   = (const int*)d_in[7];
    const int*   kiso   = (const int*)d_in[8];
    const float* g1w    = (const float*)d_in[9];
    const float* g1b    = (const float*)d_in[10];
    const float* g2w    = (const float*)d_in[11];
    const float* g2b    = (const float*)d_in[12];
    const float* h1w    = (const float*)d_in[13];
    const float* h1b    = (const float*)d_in[14];
    const float* h2w    = (const float*)d_in[15];
    const float* h2b    = (const float*)d_in[16];
    const float* f1w    = (const float*)d_in[17];
    const float* f1b    = (const float*)d_in[18];
    const float* f2w    = (const float*)d_in[19];
    const float* f2b    = (const float*)d_in[20];
    const float* ln1g   = (const float*)d_in[21];
    const float* ln1b   = (const float*)d_in[22];
    const float* ln2g   = (const float*)d_in[23];
    const float* ln2b   = (const float*)d_in[24];
    float* out = (float*)d_out;

    float *pR, *pL, *pAO, *pX, *pF1, *pF2;
    cudaGetSymbolAddress((void**)&pR,  g_R);
    cudaGetSymbolAddress((void**)&pL,  g_L);
    cudaGetSymbolAddress((void**)&pAO, g_AO);
    cudaGetSymbolAddress((void**)&pX,  g_X);
    cudaGetSymbolAddress((void**)&pF1, g_F1);
    cudaGetSymbolAddress((void**)&pF2, g_F2);

    reduce_k<<<dim3(RBLK, 2), 256>>>(qA, kA, qco, kco, qiso, kiso);
    reduce2_k<<<(2 * 15 * K_CL) / 256, 256>>>();
    cfeat_k<<<K_CL / 256, 256>>>(sensor, g1w, g1b, h1w, h1b);
    rfactor_k<<<dim3(16, 16), 256>>>(g2w, g2b, h2w, h2b, h1w);

    // logits = (Q @ K^T)/16 * R
    gemm_k4<128, 1, true><<<dim3(16, 8), 256>>>(query, keyemb, pL, K_CL, K_CL, DM, pR, 0.0625f);
    softmax_k<<<K_CL, 256>>>(pL);
    // attn @ key_emb
    gemm_k4<32, 0, false><<<dim3(4, 32), 256>>>(pL, keyemb, pAO, K_CL, DM, K_CL, nullptr, 1.f);
    add_ln_k<<<K_CL, 256>>>(query, pAO, ln1g, ln1b, pX);
    // FFN1
    gemm_k4<128, 2, false><<<dim3(16, 8), 256>>>(pX, f1w, pF1, K_CL, 4 * DM, DM, f1b, 1.f);
    // FFN2
    gemm_k4<32, 3, false><<<dim3(4, 32), 256>>>(pF1, f2w, pF2, K_CL, DM, 4 * DM, f2b, 1.f);
    add_ln_k<<<K_CL, 256>>>(pX, pF2, ln2g, ln2b, out);
}

// round 9
// speedup vs baseline: 1.1562x; 1.1562x over previous
#include <cuda_runtime.h>
#include <math.h>
#include <stdint.h>
#include <mma.h>
#include <type_traits>

using namespace nvcuda;

#define K_CL 1024
#define DM   256
#define NPX  65536
#define NISO 12
#define RBLK 304
#define CHUNK 216

// ---------------- device scratch ----------------
__device__ float g_part[2 * RBLK * 15 * K_CL];
__device__ float g_S[2 * 15 * K_CL];
__device__ float g_GU[K_CL * 32];
__device__ float g_GV[K_CL * 32];
__device__ float g_HA[K_CL * 32];
__device__ float g_HB[K_CL * 32];
__device__ float g_QC[K_CL * 2];
__device__ float g_KC[K_CL * 2];
__device__ float g_R[K_CL * K_CL];
__device__ float g_L[K_CL * K_CL];
__device__ float g_AO[K_CL * DM];
__device__ float g_X[K_CL * DM];
__device__ float g_F1[K_CL * 4 * DM];
__device__ float g_F2[K_CL * DM];

// ---------------- kernel 1: fused A^T reductions (sequential, HBM bound) ----------
__launch_bounds__(256)
__global__ void reduce_k(const float* __restrict__ qA, const float* __restrict__ kA,
                         const float* __restrict__ qco, const float* __restrict__ kco,
                         const int* __restrict__ qiso, const int* __restrict__ kiso)
{
    __shared__ float4 sIso[NISO * 256];   // 48KB
    const int tid = threadIdx.x;
    const int bx  = blockIdx.x;
    const int mat = blockIdx.y;
    const float* __restrict__ A   = mat ? kA   : qA;
    const float2* __restrict__ co2 = (const float2*)(mat ? kco : qco);
    const int*   __restrict__ iso = mat ? kiso : qiso;

    for (int i = tid; i < NISO * 256; i += 256) sIso[i] = make_float4(0.f, 0.f, 0.f, 0.f);
    __syncthreads();

    float4 sx = make_float4(0,0,0,0), sy = sx, ss = sx;

    const int base = bx * CHUNK;
    const int end  = (base + CHUNK < NPX) ? base + CHUNK : NPX;
    const float4* __restrict__ A4 = (const float4*)A;

    for (int r = base; r < end; r += 4) {
        float4 a0 = A4[(size_t)(r+0) * 256 + tid];
        float4 a1 = A4[(size_t)(r+1) * 256 + tid];
        float4 a2 = A4[(size_t)(r+2) * 256 + tid];
        float4 a3 = A4[(size_t)(r+3) * 256 + tid];
        float2 c0 = __ldg(co2 + r+0), c1 = __ldg(co2 + r+1);
        float2 c2 = __ldg(co2 + r+2), c3 = __ldg(co2 + r+3);
        int i0 = __ldg(iso + r+0) - 1, i1 = __ldg(iso + r+1) - 1;
        int i2 = __ldg(iso + r+2) - 1, i3 = __ldg(iso + r+3) - 1;

        #define ACC(a, c, ic) do { \
            sx.x = fmaf(a.x, c.x, sx.x); sx.y = fmaf(a.y, c.x, sx.y); \
            sx.z = fmaf(a.z, c.x, sx.z); sx.w = fmaf(a.w, c.x, sx.w); \
            sy.x = fmaf(a.x, c.y, sy.x); sy.y = fmaf(a.y, c.y, sy.y); \
            sy.z = fmaf(a.z, c.y, sy.z); sy.w = fmaf(a.w, c.y, sy.w); \
            ss.x += a.x; ss.y += a.y; ss.z += a.z; ss.w += a.w; \
            float4 t = sIso[(ic) * 256 + tid]; \
            t.x += a.x; t.y += a.y; t.z += a.z; t.w += a.w; \
            sIso[(ic) * 256 + tid] = t; } while (0)

        ACC(a0, c0, i0); ACC(a1, c1, i1); ACC(a2, c2, i2); ACC(a3, c3, i3);
        #undef ACC
    }

    float4* P4 = (float4*)(g_part + (size_t)(mat * RBLK + bx) * 15 * K_CL);
    P4[0 * 256 + tid] = sx;
    P4[1 * 256 + tid] = sy;
    P4[2 * 256 + tid] = ss;
    #pragma unroll
    for (int c = 0; c < NISO; c++)
        P4[(3 + c) * 256 + tid] = sIso[c * 256 + tid];
}

// ---------------- kernel 2: reduce partials ----------------
__global__ void reduce2_k()
{
    int idx = blockIdx.x * 256 + threadIdx.x;
    int mat = idx / (15 * K_CL);
    int rem = idx % (15 * K_CL);
    const float* P = g_part + (size_t)mat * RBLK * 15 * K_CL + rem;
    float s = 0.f;
    #pragma unroll 8
    for (int b = 0; b < RBLK; b++) s += P[(size_t)b * 15 * K_CL];
    g_S[idx] = s;
}

// ---------------- kernel 3: per-cluster features ----------------
__global__ void cfeat_k(const float* __restrict__ sensor,
                        const float* __restrict__ g1w, const float* __restrict__ g1b,
                        const float* __restrict__ h1w, const float* __restrict__ h1b)
{
    int k = blockIdx.x * 256 + threadIdx.x;
    float dq[NISO], dkp[NISO];

    float sq  = g_S[(0*15 + 2)*K_CL + k];
    float qcx = g_S[(0*15 + 0)*K_CL + k] / (sq + 1e-6f);
    float qcy = g_S[(0*15 + 1)*K_CL + k] / (sq + 1e-6f);
    float sk  = g_S[(1*15 + 2)*K_CL + k];
    float kcx = g_S[(1*15 + 0)*K_CL + k] / (sk + 1e-6f);
    float kcy = g_S[(1*15 + 1)*K_CL + k] / (sk + 1e-6f);

    float sum0 = 0.f, sum1 = 0.f;
    #pragma unroll
    for (int c = 0; c < NISO; c++) {
        dq[c]  = g_S[(0*15 + 3 + c)*K_CL + k];  sum0 += dq[c];
        dkp[c] = g_S[(1*15 + 3 + c)*K_CL + k];  sum1 += dkp[c];
    }
    #pragma unroll
    for (int c = 0; c < NISO; c++) { dq[c] /= sum0; dkp[c] /= sum1; }

    float sxn = sensor[0], syn = sensor[1];
    float nks  = sqrtf((qcx - sxn)*(qcx - sxn) + (qcy - syn)*(qcy - syn));
    float nkps = sqrtf((kcx - sxn)*(kcx - sxn) + (kcy - syn)*(kcy - syn));

    g_QC[2*k] = qcx; g_QC[2*k+1] = qcy;
    g_KC[2*k] = kcx; g_KC[2*k+1] = kcy;

    for (int o = 0; o < 32; o++) {
        float u = g1b[o], v = 0.f;
        #pragma unroll
        for (int c = 0; c < NISO; c++) {
            u = fmaf(dq[c],  g1w[c*32 + o],          u);
            v = fmaf(dkp[c], g1w[(NISO + c)*32 + o], v);
        }
        g_GU[k*32 + o] = u;
        g_GV[k*32 + o] = v;
        g_HA[k*32 + o] = fmaf(nks, h1w[32 + o], h1b[o]);
        g_HB[k*32 + o] = nkps * h1w[64 + o];
    }
}

// ---------------- kernel 4: R factor ----------------
__launch_bounds__(256)
__global__ void rfactor_k(const float* __restrict__ g2w, const float* __restrict__ g2b,
                          const float* __restrict__ h2w, const float* __restrict__ h2b,
                          const float* __restrict__ h1w)
{
    __shared__ float sGU[32][68], sGV[32][68], sHA[32][68], sHB[32][68];
    __shared__ float sW[96];
    __shared__ float sQC[64][2], sKC[64][2];

    const int tid = threadIdx.x;
    const int ib = blockIdx.y * 64, jb = blockIdx.x * 64;

    #pragma unroll
    for (int p = 0; p < 2; p++) {
        int idx = tid + p * 256;
        int row = idx >> 3, c0 = (idx & 7) * 4;
        float4 u = *(const float4*)&g_GU[(ib + row)*32 + c0];
        sGU[c0][row] = u.x; sGU[c0+1][row] = u.y; sGU[c0+2][row] = u.z; sGU[c0+3][row] = u.w;
        float4 v = *(const float4*)&g_GV[(jb + row)*32 + c0];
        sGV[c0][row] = v.x; sGV[c0+1][row] = v.y; sGV[c0+2][row] = v.z; sGV[c0+3][row] = v.w;
        float4 a = *(const float4*)&g_HA[(ib + row)*32 + c0];
        sHA[c0][row] = a.x; sHA[c0+1][row] = a.y; sHA[c0+2][row] = a.z; sHA[c0+3][row] = a.w;
        float4 b = *(const float4*)&g_HB[(jb + row)*32 + c0];
        sHB[c0][row] = b.x; sHB[c0+1][row] = b.y; sHB[c0+2][row] = b.z; sHB[c0+3][row] = b.w;
    }
    if (tid < 32)       sW[tid] = g2w[tid];
    else if (tid < 64)  sW[tid] = h2w[tid - 32];
    else if (tid < 96)  sW[tid] = h1w[tid - 64];
    if (tid < 128)      sQC[tid >> 1][tid & 1] = g_QC[(ib + (tid >> 1))*2 + (tid & 1)];
    else                { int t = tid - 128; sKC[t >> 1][t & 1] = g_KC[(jb + (t >> 1))*2 + (t & 1)]; }
    __syncthreads();

    const int ty = tid >> 4, tx = tid & 15;
    float nkk[4][4];
    #pragma unroll
    for (int m = 0; m < 4; m++) {
        float qx = sQC[ty*4 + m][0], qy = sQC[ty*4 + m][1];
        #pragma unroll
        for (int n = 0; n < 4; n++) {
            float dx = qx - sKC[tx*4 + n][0], dy = qy - sKC[tx*4 + n][1];
            nkk[m][n] = sqrtf(dx*dx + dy*dy);
        }
    }

    float gacc[4][4], hacc[4][4];
    #pragma unroll
    for (int m = 0; m < 4; m++)
        #pragma unroll
        for (int n = 0; n < 4; n++) { gacc[m][n] = 0.f; hacc[m][n] = 0.f; }

    #pragma unroll 4
    for (int c = 0; c < 32; c++) {
        float gw = sW[c], hw = sW[32 + c], w1c = sW[64 + c];
        float4 au = *(const float4*)&sGU[c][ty*4];
        float4 aa = *(const float4*)&sHA[c][ty*4];
        float4 bv = *(const float4*)&sGV[c][tx*4];
        float4 bb = *(const float4*)&sHB[c][tx*4];
        const float* aup = &au.x; const float* aap = &aa.x;
        const float* bvp = &bv.x; const float* bbp = &bb.x;
        #pragma unroll
        for (int m = 0; m < 4; m++)
            #pragma unroll
            for (int n = 0; n < 4; n++) {
                float g = fmaxf(aup[m] + bvp[n], 0.f);
                gacc[m][n] = fmaf(g, gw, gacc[m][n]);
                float h = fmaxf(fmaf(nkk[m][n], w1c, aap[m] + bbp[n]), 0.f);
                hacc[m][n] = fmaf(h, hw, hacc[m][n]);
            }
    }

    const float g2b0 = g2b[0], h2b0 = h2b[0];
    #pragma unroll
    for (int m = 0; m < 4; m++) {
        float4 o;
        float* op = &o.x;
        #pragma unroll
        for (int n = 0; n < 4; n++)
            op[n] = fmaxf(gacc[m][n] + g2b0, 0.f) * fmaxf(hacc[m][n] + h2b0, 0.f);
        *(float4*)&g_R[(size_t)(ib + ty*4 + m) * K_CL + jb + tx*4] = o;
    }
}

// ---------------- tensor-core tf32 GEMM (3xTF32 split, wmma m16n16k8) ----------------
// Block tile 128x64, 8 warps (4m x 2n), warp tile 32x32 (2x2 wmma frags).
// As[m][20] (row-major, ld 20). BT: Bs[n][20] col-major frag; nonBT: Bs[k][68] row-major frag.
// D = Ahi*Bhi + Ahi*Blo + Alo*Bhi  (error ~2^-22).
// MODE 0: store; 1: *scale*ext[i*N+j]; 2: relu(+ext[j]); 3: +ext[j].
template<int MODE, bool BT>
__launch_bounds__(256)
__global__ void gemm_tc(const float* __restrict__ A, const float* __restrict__ B,
                        float* __restrict__ C, int M, int N, int Kd,
                        const float* __restrict__ ext, float scale)
{
    constexpr int TM = 128, TN = 64;
    constexpr int LDA = 20;
    constexpr int BROWS = BT ? TN : 16;
    constexpr int LDB   = BT ? 20 : 68;

    __shared__ float As[2][TM][LDA];
    __shared__ float Bs[2][BROWS][LDB];
    __shared__ float Cs[TM][TN];

    const int tid = threadIdx.x;
    const int row0 = blockIdx.y * TM, col0 = blockIdx.x * TN;
    const int wid = tid >> 5;
    const int wm = wid >> 1;         // 0..3
    const int wn = wid & 1;          // 0..1
    const int mbase = wm * 32, nbase = wn * 32;

    float4 ra[2];
    float4 rb;

    auto ldTile = [&](int k0) {
        #pragma unroll
        for (int i = 0; i < 2; i++) {
            int idx = tid + i * 256;
            int lr = idx >> 2, lc = (idx & 3) * 4;
            ra[i] = *(const float4*)(A + (size_t)(row0 + lr) * Kd + k0 + lc);
        }
        if (BT) {
            int lr = tid >> 2, lc = (tid & 3) * 4;
            rb = *(const float4*)(B + (size_t)(col0 + lr) * Kd + k0 + lc);
        } else {
            int lr = tid >> 4, lc = (tid & 15) * 4;
            rb = *(const float4*)(B + (size_t)(k0 + lr) * N + col0 + lc);
        }
    };
    auto stTile = [&](int buf) {
        #pragma unroll
        for (int i = 0; i < 2; i++) {
            int idx = tid + i * 256;
            int lr = idx >> 2, lc = (idx & 3) * 4;
            *(float4*)&As[buf][lr][lc] = ra[i];
        }
        if (BT) {
            int lr = tid >> 2, lc = (tid & 3) * 4;
            *(float4*)&Bs[buf][lr][lc] = rb;
        } else {
            int lr = tid >> 4, lc = (tid & 15) * 4;
            *(float4*)&Bs[buf][lr][lc] = rb;
        }
    };

    typedef wmma::fragment<wmma::matrix_a, 16, 16, 8, wmma::precision::tf32, wmma::row_major> FragA;
    typedef wmma::fragment<wmma::matrix_b, 16, 16, 8, wmma::precision::tf32,
                           std::conditional_t<BT, wmma::col_major, wmma::row_major>> FragB;
    typedef wmma::fragment<wmma::accumulator, 16, 16, 8, float> FragC;

    FragC c[2][2];
    #pragma unroll
    for (int i = 0; i < 2; i++)
        #pragma unroll
        for (int j = 0; j < 2; j++) wmma::fill_fragment(c[i][j], 0.f);

    const int nt = Kd >> 4;
    ldTile(0);
    stTile(0);
    __syncthreads();

    for (int t = 0; t < nt; t++) {
        const int cur = t & 1;
        if (t + 1 < nt) ldTile((t + 1) << 4);

        #pragma unroll
        for (int k8 = 0; k8 < 16; k8 += 8) {
            FragA ahi[2], alo[2];
            #pragma unroll
            for (int i = 0; i < 2; i++) {
                FragA ar;
                wmma::load_matrix_sync(ar, &As[cur][mbase + 16 * i][k8], LDA);
                #pragma unroll
                for (int e = 0; e < ar.num_elements; e++) {
                    float hv = wmma::__float_to_tf32(ar.x[e]);
                    ahi[i].x[e] = hv;
                    alo[i].x[e] = wmma::__float_to_tf32(ar.x[e] - hv);
                }
            }
            FragB bhi[2], blo[2];
            #pragma unroll
            for (int j = 0; j < 2; j++) {
                FragB br;
                if (BT) wmma::load_matrix_sync(br, &Bs[cur][nbase + 16 * j][k8], LDB);
                else    wmma::load_matrix_sync(br, &Bs[cur][k8][nbase + 16 * j], LDB);
                #pragma unroll
                for (int e = 0; e < br.num_elements; e++) {
                    float hv = wmma::__float_to_tf32(br.x[e]);
                    bhi[j].x[e] = hv;
                    blo[j].x[e] = wmma::__float_to_tf32(br.x[e] - hv);
                }
            }
            #pragma unroll
            for (int i = 0; i < 2; i++)
                #pragma unroll
                for (int j = 0; j < 2; j++) {
                    wmma::mma_sync(c[i][j], ahi[i], bhi[j], c[i][j]);
                    wmma::mma_sync(c[i][j], ahi[i], blo[j], c[i][j]);
                    wmma::mma_sync(c[i][j], alo[i], bhi[j], c[i][j]);
                }
        }

        if (t + 1 < nt) {
            stTile((t + 1) & 1);
        }
        __syncthreads();
    }

    // epilogue via smem staging
    #pragma unroll
    for (int i = 0; i < 2; i++)
        #pragma unroll
        for (int j = 0; j < 2; j++)
            wmma::store_matrix_sync(&Cs[mbase + 16 * i][nbase + 16 * j], c[i][j], TN, wmma::mem_row_major);
    __syncthreads();

    #pragma unroll
    for (int p = 0; p < 8; p++) {
        int idx = tid + p * 256;
        int r = idx >> 4, c4 = (idx & 15) * 4;
        float4 v = *(const float4*)&Cs[r][c4];
        int i = row0 + r, j0 = col0 + c4;
        if (MODE == 1) {
            float4 rr = *(const float4*)(ext + (size_t)i * N + j0);
            v.x = v.x * scale * rr.x; v.y = v.y * scale * rr.y;
            v.z = v.z * scale * rr.z; v.w = v.w * scale * rr.w;
        } else if (MODE == 2) {
            v.x = fmaxf(v.x + ext[j0+0], 0.f); v.y = fmaxf(v.y + ext[j0+1], 0.f);
            v.z = fmaxf(v.z + ext[j0+2], 0.f); v.w = fmaxf(v.w + ext[j0+3], 0.f);
        } else if (MODE == 3) {
            v.x += ext[j0+0]; v.y += ext[j0+1]; v.z += ext[j0+2]; v.w += ext[j0+3];
        }
        *(float4*)(C + (size_t)i * N + j0) = v;
    }
}

// ---------------- softmax ----------------
__global__ void softmax_k(float* __restrict__ X)
{
    const int row = blockIdx.x, tid = threadIdx.x;
    __shared__ float red[256];
    float v[4];
    float m = -3.4e38f;
    #pragma unroll
    for (int j = 0; j < 4; j++) { v[j] = X[(size_t)row * K_CL + tid + j * 256]; m = fmaxf(m, v[j]); }
    red[tid] = m; __syncthreads();
    #pragma unroll
    for (int s = 128; s > 0; s >>= 1) { if (tid < s) red[tid] = fmaxf(red[tid], red[tid + s]); __syncthreads(); }
    m = red[0]; __syncthreads();
    float sum = 0.f;
    #pragma unroll
    for (int j = 0; j < 4; j++) { v[j] = __expf(v[j] - m); sum += v[j]; }
    red[tid] = sum; __syncthreads();
    #pragma unroll
    for (int s = 128; s > 0; s >>= 1) { if (tid < s) red[tid] += red[tid + s]; __syncthreads(); }
    float inv = 1.f / red[0];
    #pragma unroll
    for (int j = 0; j < 4; j++) X[(size_t)row * K_CL + tid + j * 256] = v[j] * inv;
}

// ---------------- residual add + LayerNorm ----------------
__global__ void add_ln_k(const float* __restrict__ a, const float* __restrict__ b,
                         const float* __restrict__ g, const float* __restrict__ be,
                         float* __restrict__ out)
{
    const int row = blockIdx.x, tid = threadIdx.x;
    __shared__ float red[256];
    float x = a[row * DM + tid] + b[row * DM + tid];
    red[tid] = x; __syncthreads();
    #pragma unroll
    for (int s = 128; s > 0; s >>= 1) { if (tid < s) red[tid] += red[tid + s]; __syncthreads(); }
    float mean = red[0] * (1.f / DM); __syncthreads();
    float d = x - mean;
    red[tid] = d * d; __syncthreads();
    #pragma unroll
    for (int s = 128; s > 0; s >>= 1) { if (tid < s) red[tid] += red[tid + s]; __syncthreads(); }
    float var = red[0] * (1.f / DM);
    out[row * DM + tid] = d * rsqrtf(var + 1e-6f) * g[tid] + be[tid];
}

// ---------------- launch ----------------
extern "C" void kernel_launch(void* const* d_in, const int* in_sizes, int n_in,
                              void* d_out, int out_size)
{
    const float* sensor = (const float*)d_in[0];
    const float* query  = (const float*)d_in[1];
    const float* keyemb = (const float*)d_in[2];
    const float* qA     = (const float*)d_in[3];
    const float* kA     = (const float*)d_in[4];
    const float* qco    = (const float*)d_in[5];
    const float* kco    = (const float*)d_in[6];
    const int*   qiso   = (const int*)d_in[7];
    const int*   kiso   = (const int*)d_in[8];
    const float* g1w    = (const float*)d_in[9];
    const float* g1b    = (const float*)d_in[10];
    const float* g2w    = (const float*)d_in[11];
    const float* g2b    = (const float*)d_in[12];
    const float* h1w    = (const float*)d_in[13];
    const float* h1b    = (const float*)d_in[14];
    const float* h2w    = (const float*)d_in[15];
    const float* h2b    = (const float*)d_in[16];
    const float* f1w    = (const float*)d_in[17];
    const float* f1b    = (const float*)d_in[18];
    const float* f2w    = (const float*)d_in[19];
    const float* f2b    = (const float*)d_in[20];
    const float* ln1g   = (const float*)d_in[21];
    const float* ln1b   = (const float*)d_in[22];
    const float* ln2g   = (const float*)d_in[23];
    const float* ln2b   = (const float*)d_in[24];
    float* out = (float*)d_out;

    float *pR, *pL, *pAO, *pX, *pF1, *pF2;
    cudaGetSymbolAddress((void**)&pR,  g_R);
    cudaGetSymbolAddress((void**)&pL,  g_L);
    cudaGetSymbolAddress((void**)&pAO, g_AO);
    cudaGetSymbolAddress((void**)&pX,  g_X);
    cudaGetSymbolAddress((void**)&pF1, g_F1);
    cudaGetSymbolAddress((void**)&pF2, g_F2);

    reduce_k<<<dim3(RBLK, 2), 256>>>(qA, kA, qco, kco, qiso, kiso);
    reduce2_k<<<(2 * 15 * K_CL) / 256, 256>>>();
    cfeat_k<<<K_CL / 256, 256>>>(sensor, g1w, g1b, h1w, h1b);
    rfactor_k<<<dim3(16, 16), 256>>>(g2w, g2b, h2w, h2b, h1w);

    // logits = (Q @ K^T)/16 * R        (M=1024, N=1024, K=256)
    gemm_tc<1, true><<<dim3(16, 8), 256>>>(query, keyemb, pL, K_CL, K_CL, DM, pR, 0.0625f);
    softmax_k<<<K_CL, 256>>>(pL);
    // attn @ key_emb                   (M=1024, N=256, K=1024)
    gemm_tc<0, false><<<dim3(4, 8), 256>>>(pL, keyemb, pAO, K_CL, DM, K_CL, nullptr, 1.f);
    add_ln_k<<<K_CL, 256>>>(query, pAO, ln1g, ln1b, pX);
    // FFN1: relu(x @ w1 + b1)          (M=1024, N=1024, K=256)
    gemm_tc<2, false><<<dim3(16, 8), 256>>>(pX, f1w, pF1, K_CL, 4 * DM, DM, f1b, 1.f);
    // FFN2: h @ w2 + b2                (M=1024, N=256, K=1024)
    gemm_tc<3, false><<<dim3(4, 8), 256>>>(pF1, f2w, pF2, K_CL, DM, 4 * DM, f2b, 1.f);
    add_ln_k<<<K_CL, 256>>>(pX, pF2, ln2g, ln2b, out);
}

// round 11
// speedup vs baseline: 1.8130x; 1.5681x over previous
#include <cuda_runtime.h>
#include <math.h>
#include <stdint.h>

#define K_CL 1024
#define DM   256
#define NPX  65536
#define NISO 12
#define RBLK 304
#define CHUNK 216

typedef unsigned long long u64;

__device__ __forceinline__ u64 pack2(float lo, float hi) {
    u64 r;
    asm("mov.b64 %0, {%1, %2};" : "=l"(r)
        : "r"(__float_as_uint(lo)), "r"(__float_as_uint(hi)));
    return r;
}
__device__ __forceinline__ void unpack2(u64 v, float& lo, float& hi) {
    unsigned a, b;
    asm("mov.b64 {%0, %1}, %2;" : "=r"(a), "=r"(b) : "l"(v));
    lo = __uint_as_float(a); hi = __uint_as_float(b);
}
__device__ __forceinline__ u64 fma2(u64 a, u64 b, u64 c) {
    u64 d;
    asm("fma.rn.f32x2 %0, %1, %2, %3;" : "=l"(d) : "l"(a), "l"(b), "l"(c));
    return d;
}

// ---------------- device scratch ----------------
__device__ float g_part[2 * RBLK * 15 * K_CL];
__device__ float g_S[2 * 15 * K_CL];
__device__ float g_GU[K_CL * 32];
__device__ float g_GV[K_CL * 32];
__device__ float g_HA[K_CL * 32];
__device__ float g_HB[K_CL * 32];
__device__ float g_QC[K_CL * 2];
__device__ float g_KC[K_CL * 2];
__device__ float g_R[K_CL * K_CL];
__device__ float g_L[K_CL * K_CL];
__device__ float g_X[K_CL * DM];
__device__ float g_F1[K_CL * 4 * DM];
__device__ float g_P[2 * K_CL * DM];     // split-K partials

// ---------------- kernel 1: fused A^T reductions (sequential, HBM bound) ----------
__launch_bounds__(256)
__global__ void reduce_k(const float* __restrict__ qA, const float* __restrict__ kA,
                         const float* __restrict__ qco, const float* __restrict__ kco,
                         const int* __restrict__ qiso, const int* __restrict__ kiso)
{
    __shared__ float4 sIso[NISO * 256];   // 48KB
    const int tid = threadIdx.x;
    const int bx  = blockIdx.x;
    const int mat = blockIdx.y;
    const float* __restrict__ A    = mat ? kA   : qA;
    const float2* __restrict__ co2 = (const float2*)(mat ? kco : qco);
    const int*   __restrict__ iso  = mat ? kiso : qiso;

    for (int i = tid; i < NISO * 256; i += 256) sIso[i] = make_float4(0.f, 0.f, 0.f, 0.f);
    __syncthreads();

    float4 sx = make_float4(0,0,0,0), sy = sx, ss = sx;

    const int base = bx * CHUNK;
    const int end  = (base + CHUNK < NPX) ? base + CHUNK : NPX;
    const float4* __restrict__ A4 = (const float4*)A;

    for (int r = base; r < end; r += 4) {
        float4 a0 = A4[(size_t)(r+0) * 256 + tid];
        float4 a1 = A4[(size_t)(r+1) * 256 + tid];
        float4 a2 = A4[(size_t)(r+2) * 256 + tid];
        float4 a3 = A4[(size_t)(r+3) * 256 + tid];
        float2 c0 = __ldg(co2 + r+0), c1 = __ldg(co2 + r+1);
        float2 c2 = __ldg(co2 + r+2), c3 = __ldg(co2 + r+3);
        int i0 = __ldg(iso + r+0) - 1, i1 = __ldg(iso + r+1) - 1;
        int i2 = __ldg(iso + r+2) - 1, i3 = __ldg(iso + r+3) - 1;

        #define ACC(a, c, ic) do { \
            sx.x = fmaf(a.x, c.x, sx.x); sx.y = fmaf(a.y, c.x, sx.y); \
            sx.z = fmaf(a.z, c.x, sx.z); sx.w = fmaf(a.w, c.x, sx.w); \
            sy.x = fmaf(a.x, c.y, sy.x); sy.y = fmaf(a.y, c.y, sy.y); \
            sy.z = fmaf(a.z, c.y, sy.z); sy.w = fmaf(a.w, c.y, sy.w); \
            ss.x += a.x; ss.y += a.y; ss.z += a.z; ss.w += a.w; \
            float4 t = sIso[(ic) * 256 + tid]; \
            t.x += a.x; t.y += a.y; t.z += a.z; t.w += a.w; \
            sIso[(ic) * 256 + tid] = t; } while (0)

        ACC(a0, c0, i0); ACC(a1, c1, i1); ACC(a2, c2, i2); ACC(a3, c3, i3);
        #undef ACC
    }

    float4* P4 = (float4*)(g_part + (size_t)(mat * RBLK + bx) * 15 * K_CL);
    P4[0 * 256 + tid] = sx;
    P4[1 * 256 + tid] = sy;
    P4[2 * 256 + tid] = ss;
    #pragma unroll
    for (int c = 0; c < NISO; c++)
        P4[(3 + c) * 256 + tid] = sIso[c * 256 + tid];
}

// ---------------- kernel 2: reduce partials ----------------
__global__ void reduce2_k()
{
    int idx = blockIdx.x * 256 + threadIdx.x;
    int mat = idx / (15 * K_CL);
    int rem = idx % (15 * K_CL);
    const float* P = g_part + (size_t)mat * RBLK * 15 * K_CL + rem;
    float s = 0.f;
    #pragma unroll 8
    for (int b = 0; b < RBLK; b++) s += P[(size_t)b * 15 * K_CL];
    g_S[idx] = s;
}

// ---------------- kernel 3: per-cluster features ----------------
__global__ void cfeat_k(const float* __restrict__ sensor,
                        const float* __restrict__ g1w, const float* __restrict__ g1b,
                        const float* __restrict__ h1w, const float* __restrict__ h1b)
{
    int k = blockIdx.x * 256 + threadIdx.x;
    float dq[NISO], dkp[NISO];

    float sq  = g_S[(0*15 + 2)*K_CL + k];
    float qcx = g_S[(0*15 + 0)*K_CL + k] / (sq + 1e-6f);
    float qcy = g_S[(0*15 + 1)*K_CL + k] / (sq + 1e-6f);
    float sk  = g_S[(1*15 + 2)*K_CL + k];
    float kcx = g_S[(1*15 + 0)*K_CL + k] / (sk + 1e-6f);
    float kcy = g_S[(1*15 + 1)*K_CL + k] / (sk + 1e-6f);

    float sum0 = 0.f, sum1 = 0.f;
    #pragma unroll
    for (int c = 0; c < NISO; c++) {
        dq[c]  = g_S[(0*15 + 3 + c)*K_CL + k];  sum0 += dq[c];
        dkp[c] = g_S[(1*15 + 3 + c)*K_CL + k];  sum1 += dkp[c];
    }
    #pragma unroll
    for (int c = 0; c < NISO; c++) { dq[c] /= sum0; dkp[c] /= sum1; }

    float sxn = sensor[0], syn = sensor[1];
    float nks  = sqrtf((qcx - sxn)*(qcx - sxn) + (qcy - syn)*(qcy - syn));
    float nkps = sqrtf((kcx - sxn)*(kcx - sxn) + (kcy - syn)*(kcy - syn));

    g_QC[2*k] = qcx; g_QC[2*k+1] = qcy;
    g_KC[2*k] = kcx; g_KC[2*k+1] = kcy;

    for (int o = 0; o < 32; o++) {
        float u = g1b[o], v = 0.f;
        #pragma unroll
        for (int c = 0; c < NISO; c++) {
            u = fmaf(dq[c],  g1w[c*32 + o],          u);
            v = fmaf(dkp[c], g1w[(NISO + c)*32 + o], v);
        }
        g_GU[k*32 + o] = u;
        g_GV[k*32 + o] = v;
        g_HA[k*32 + o] = fmaf(nks, h1w[32 + o], h1b[o]);
        g_HB[k*32 + o] = nkps * h1w[64 + o];
    }
}

// ---------------- kernel 4: R factor ----------------
__launch_bounds__(256)
__global__ void rfactor_k(const float* __restrict__ g2w, const float* __restrict__ g2b,
                          const float* __restrict__ h2w, const float* __restrict__ h2b,
                          const float* __restrict__ h1w)
{
    __shared__ float sGU[32][68], sGV[32][68], sHA[32][68], sHB[32][68];
    __shared__ float sW[96];
    __shared__ float sQC[64][2], sKC[64][2];

    const int tid = threadIdx.x;
    const int ib = blockIdx.y * 64, jb = blockIdx.x * 64;

    #pragma unroll
    for (int p = 0; p < 2; p++) {
        int idx = tid + p * 256;
        int row = idx >> 3, c0 = (idx & 7) * 4;
        float4 u = *(const float4*)&g_GU[(ib + row)*32 + c0];
        sGU[c0][row] = u.x; sGU[c0+1][row] = u.y; sGU[c0+2][row] = u.z; sGU[c0+3][row] = u.w;
        float4 v = *(const float4*)&g_GV[(jb + row)*32 + c0];
        sGV[c0][row] = v.x; sGV[c0+1][row] = v.y; sGV[c0+2][row] = v.z; sGV[c0+3][row] = v.w;
        float4 a = *(const float4*)&g_HA[(ib + row)*32 + c0];
        sHA[c0][row] = a.x; sHA[c0+1][row] = a.y; sHA[c0+2][row] = a.z; sHA[c0+3][row] = a.w;
        float4 b = *(const float4*)&g_HB[(jb + row)*32 + c0];
        sHB[c0][row] = b.x; sHB[c0+1][row] = b.y; sHB[c0+2][row] = b.z; sHB[c0+3][row] = b.w;
    }
    if (tid < 32)       sW[tid] = g2w[tid];
    else if (tid < 64)  sW[tid] = h2w[tid - 32];
    else if (tid < 96)  sW[tid] = h1w[tid - 64];
    if (tid < 128)      sQC[tid >> 1][tid & 1] = g_QC[(ib + (tid >> 1))*2 + (tid & 1)];
    else                { int t = tid - 128; sKC[t >> 1][t & 1] = g_KC[(jb + (t >> 1))*2 + (t & 1)]; }
    __syncthreads();

    const int ty = tid >> 4, tx = tid & 15;
    float nkk[4][4];
    #pragma unroll
    for (int m = 0; m < 4; m++) {
        float qx = sQC[ty*4 + m][0], qy = sQC[ty*4 + m][1];
        #pragma unroll
        for (int n = 0; n < 4; n++) {
            float dx = qx - sKC[tx*4 + n][0], dy = qy - sKC[tx*4 + n][1];
            nkk[m][n] = sqrtf(dx*dx + dy*dy);
        }
    }

    float gacc[4][4], hacc[4][4];
    #pragma unroll
    for (int m = 0; m < 4; m++)
        #pragma unroll
        for (int n = 0; n < 4; n++) { gacc[m][n] = 0.f; hacc[m][n] = 0.f; }

    #pragma unroll 4
    for (int c = 0; c < 32; c++) {
        float gw = sW[c], hw = sW[32 + c], w1c = sW[64 + c];
        float4 au = *(const float4*)&sGU[c][ty*4];
        float4 aa = *(const float4*)&sHA[c][ty*4];
        float4 bv = *(const float4*)&sGV[c][tx*4];
        float4 bb = *(const float4*)&sHB[c][tx*4];
        const float* aup = &au.x; const float* aap = &aa.x;
        const float* bvp = &bv.x; const float* bbp = &bb.x;
        #pragma unroll
        for (int m = 0; m < 4; m++)
            #pragma unroll
            for (int n = 0; n < 4; n++) {
                float g = fmaxf(aup[m] + bvp[n], 0.f);
                gacc[m][n] = fmaf(g, gw, gacc[m][n]);
                float h = fmaxf(fmaf(nkk[m][n], w1c, aap[m] + bbp[n]), 0.f);
                hacc[m][n] = fmaf(h, hw, hacc[m][n]);
            }
    }

    const float g2b0 = g2b[0], h2b0 = h2b[0];
    #pragma unroll
    for (int m = 0; m < 4; m++) {
        float4 o;
        float* op = &o.x;
        #pragma unroll
        for (int n = 0; n < 4; n++)
            op[n] = fmaxf(gacc[m][n] + g2b0, 0.f) * fmaxf(hacc[m][n] + h2b0, 0.f);
        *(float4*)&g_R[(size_t)(ib + ty*4 + m) * K_CL + jb + tx*4] = o;
    }
}

// ---------------- pipelined f32x2 GEMM (R4 proven; TM=128 only) ----------------
// MODE 1: *scale*ext[i*N+j]; 2: relu(+ext[j]).
template<int TM, int MODE, bool BT>
__launch_bounds__(256)
__global__ void gemm_k2(const float* __restrict__ A, const float* __restrict__ B,
                        float* __restrict__ C, int M, int N, int Kd,
                        const float* __restrict__ ext, float scale)
{
    constexpr int TN = 64;
    constexpr int RM = TM / 16;
    constexpr int NA = (TM * 4 + 255) / 256;
    __shared__ float As[2][16][TM];
    __shared__ float Bs[2][16][TN];

    const int tid = threadIdx.x;
    const int tx = tid & 15, ty = tid >> 4;
    const int row0 = blockIdx.y * TM, col0 = blockIdx.x * TN;

    float4 ra[NA];
    float4 rb;

    auto ldTile = [&](int k0) {
        #pragma unroll
        for (int i = 0; i < NA; i++) {
            int idx = tid + i * 256;
            if ((TM * 4) % 256 == 0 || idx < TM * 4) {
                int lr = idx >> 2, lc = (idx & 3) * 4;
                ra[i] = *(const float4*)(A + (size_t)(row0 + lr) * Kd + k0 + lc);
            }
        }
        if (BT) {
            int lr = tid >> 2, lc = (tid & 3) * 4;
            rb = *(const float4*)(B + (size_t)(col0 + lr) * Kd + k0 + lc);
        } else {
            int lr = tid >> 4, lc = (tid & 15) * 4;
            rb = *(const float4*)(B + (size_t)(k0 + lr) * N + col0 + lc);
        }
    };
    auto stTile = [&](int buf) {
        #pragma unroll
        for (int i = 0; i < NA; i++) {
            int idx = tid + i * 256;
            if ((TM * 4) % 256 == 0 || idx < TM * 4) {
                int lr = idx >> 2, lc = (idx & 3) * 4;
                As[buf][lc+0][lr] = ra[i].x; As[buf][lc+1][lr] = ra[i].y;
                As[buf][lc+2][lr] = ra[i].z; As[buf][lc+3][lr] = ra[i].w;
            }
        }
        if (BT) {
            int lr = tid >> 2, lc = (tid & 3) * 4;
            Bs[buf][lc+0][lr] = rb.x; Bs[buf][lc+1][lr] = rb.y;
            Bs[buf][lc+2][lr] = rb.z; Bs[buf][lc+3][lr] = rb.w;
        } else {
            int lr = tid >> 4, lc = (tid & 15) * 4;
            *(float4*)&Bs[buf][lr][lc] = rb;
        }
    };

    u64 acc[RM][2];
    #pragma unroll
    for (int m = 0; m < RM; m++) { acc[m][0] = 0ULL; acc[m][1] = 0ULL; }

    const int nt = Kd >> 4;
    ldTile(0);
    stTile(0);
    __syncthreads();

    for (int t = 0; t < nt; t++) {
        const int cur = t & 1;
        if (t + 1 < nt) ldTile((t + 1) << 4);

        #pragma unroll
        for (int kk = 0; kk < 16; kk++) {
            float a[RM];
            if constexpr (RM == 8) {
                float4 t0 = *(const float4*)&As[cur][kk][ty * 8];
                float4 t1 = *(const float4*)&As[cur][kk][ty * 8 + 4];
                a[0]=t0.x; a[1]=t0.y; a[2]=t0.z; a[3]=t0.w;
                a[4]=t1.x; a[5]=t1.y; a[6]=t1.z; a[7]=t1.w;
            } else {
                float2 t0 = *(const float2*)&As[cur][kk][ty * 2];
                a[0]=t0.x; a[1]=t0.y;
            }
            u64 b0 = *(const u64*)&Bs[cur][kk][tx * 4];
            u64 b1 = *(const u64*)&Bs[cur][kk][tx * 4 + 2];
            #pragma unroll
            for (int m = 0; m < RM; m++) {
                u64 aa = pack2(a[m], a[m]);
                acc[m][0] = fma2(aa, b0, acc[m][0]);
                acc[m][1] = fma2(aa, b1, acc[m][1]);
            }
        }

        if (t + 1 < nt) {
            stTile((t + 1) & 1);
            __syncthreads();
        }
    }

    #pragma unroll
    for (int m = 0; m < RM; m++) {
        int i = row0 + ty * RM + m;
        int j0 = col0 + tx * 4;
        float v0, v1, v2, v3;
        unpack2(acc[m][0], v0, v1);
        unpack2(acc[m][1], v2, v3);
        if (MODE == 1) {
            float4 r = *(const float4*)(ext + (size_t)i * N + j0);
            v0 = v0 * scale * r.x; v1 = v1 * scale * r.y;
            v2 = v2 * scale * r.z; v3 = v3 * scale * r.w;
        } else if (MODE == 2) {
            v0 = fmaxf(v0 + ext[j0+0], 0.f); v1 = fmaxf(v1 + ext[j0+1], 0.f);
            v2 = fmaxf(v2 + ext[j0+2], 0.f); v3 = fmaxf(v3 + ext[j0+3], 0.f);
        }
        float4 o; o.x = v0; o.y = v1; o.z = v2; o.w = v3;
        *(float4*)(C + (size_t)i * N + j0) = o;
    }
}

// ---------------- split-K skinny GEMM: TM=64, TN=64, RM=4, non-BT ----------------
// Partial z computes K range [z*Kd/2, (z+1)*Kd/2) into Cp + z*M*N. No epilogue.
__launch_bounds__(256)
__global__ void gemm_s(const float* __restrict__ A, const float* __restrict__ B,
                       float* __restrict__ Cp, int M, int N, int Kd)
{
    __shared__ float As[2][16][64];
    __shared__ float Bs[2][16][64];

    const int tid = threadIdx.x;
    const int tx = tid & 15, ty = tid >> 4;
    const int row0 = blockIdx.y * 64, col0 = blockIdx.x * 64;
    const int z = blockIdx.z;
    const int kbase = z * (Kd >> 1);
    float* __restrict__ C = Cp + (size_t)z * M * N;

    float4 ra, rb;
    const int alr = tid >> 2, alc = (tid & 3) * 4;   // A fill: 64 rows x 16 k
    const int blr = tid >> 4, blc = (tid & 15) * 4;  // B fill: 16 k x 64 cols

    auto ldTile = [&](int k0) {
        ra = *(const float4*)(A + (size_t)(row0 + alr) * Kd + k0 + alc);
        rb = *(const float4*)(B + (size_t)(k0 + blr) * N + col0 + blc);
    };
    auto stTile = [&](int buf) {
        As[buf][alc+0][alr] = ra.x; As[buf][alc+1][alr] = ra.y;
        As[buf][alc+2][alr] = ra.z; As[buf][alc+3][alr] = ra.w;
        *(float4*)&Bs[buf][blr][blc] = rb;
    };

    float acc[4][4];
    #pragma unroll
    for (int m = 0; m < 4; m++)
        #pragma unroll
        for (int n = 0; n < 4; n++) acc[m][n] = 0.f;

    const int nt = Kd >> 5;   // (Kd/2)/16
    ldTile(kbase);
    stTile(0);
    __syncthreads();

    for (int t = 0; t < nt; t++) {
        const int cur = t & 1;
        if (t + 1 < nt) ldTile(kbase + ((t + 1) << 4));

        #pragma unroll
        for (int kk = 0; kk < 16; kk++) {
            float4 av = *(const float4*)&As[cur][kk][ty * 4];
            float4 bv = *(const float4*)&Bs[cur][kk][tx * 4];
            const float* a = &av.x; const float* b = &bv.x;
            #pragma unroll
            for (int m = 0; m < 4; m++)
                #pragma unroll
                for (int n = 0; n < 4; n++)
                    acc[m][n] = fmaf(a[m], b[n], acc[m][n]);
        }

        if (t + 1 < nt) {
            stTile((t + 1) & 1);
            __syncthreads();
        }
    }

    #pragma unroll
    for (int m = 0; m < 4; m++) {
        int i = row0 + ty * 4 + m;
        float4 o; o.x = acc[m][0]; o.y = acc[m][1]; o.z = acc[m][2]; o.w = acc[m][3];
        *(float4*)(C + (size_t)i * N + col0 + tx * 4) = o;
    }
}

// ---------------- softmax ----------------
__global__ void softmax_k(float* __restrict__ X)
{
    const int row = blockIdx.x, tid = threadIdx.x;
    __shared__ float red[256];
    float v[4];
    float m = -3.4e38f;
    #pragma unroll
    for (int j = 0; j < 4; j++) { v[j] = X[(size_t)row * K_CL + tid + j * 256]; m = fmaxf(m, v[j]); }
    red[tid] = m; __syncthreads();
    #pragma unroll
    for (int s = 128; s > 0; s >>= 1) { if (tid < s) red[tid] = fmaxf(red[tid], red[tid + s]); __syncthreads(); }
    m = red[0]; __syncthreads();
    float sum = 0.f;
    #pragma unroll
    for (int j = 0; j < 4; j++) { v[j] = __expf(v[j] - m); sum += v[j]; }
    red[tid] = sum; __syncthreads();
    #pragma unroll
    for (int s = 128; s > 0; s >>= 1) { if (tid < s) red[tid] += red[tid + s]; __syncthreads(); }
    float inv = 1.f / red[0];
    #pragma unroll
    for (int j = 0; j < 4; j++) X[(size_t)row * K_CL + tid + j * 256] = v[j] * inv;
}

// ---------------- residual + split-K combine + LayerNorm ----------------
// x = a + p0 + p1 (+ bias[col]); out = LN(x)
template<bool BIAS>
__global__ void add_ln3_k(const float* __restrict__ a,
                          const float* __restrict__ p0, const float* __restrict__ p1,
                          const float* __restrict__ bias,
                          const float* __restrict__ g, const float* __restrict__ be,
                          float* __restrict__ out)
{
    const int row = blockIdx.x, tid = threadIdx.x;
    __shared__ float red[256];
    float x = a[row * DM + tid] + (p0[row * DM + tid] + p1[row * DM + tid]);
    if (BIAS) x += bias[tid];
    red[tid] = x; __syncthreads();
    #pragma unroll
    for (int s = 128; s > 0; s >>= 1) { if (tid < s) red[tid] += red[tid + s]; __syncthreads(); }
    float mean = red[0] * (1.f / DM); __syncthreads();
    float d = x - mean;
    red[tid] = d * d; __syncthreads();
    #pragma unroll
    for (int s = 128; s > 0; s >>= 1) { if (tid < s) red[tid] += red[tid + s]; __syncthreads(); }
    float var = red[0] * (1.f / DM);
    out[row * DM + tid] = d * rsqrtf(var + 1e-6f) * g[tid] + be[tid];
}

// ---------------- launch ----------------
extern "C" void kernel_launch(void* const* d_in, const int* in_sizes, int n_in,
                              void* d_out, int out_size)
{
    const float* sensor = (const float*)d_in[0];
    const float* query  = (const float*)d_in[1];
    const float* keyemb = (const float*)d_in[2];
    const float* qA     = (const float*)d_in[3];
    const float* kA     = (const float*)d_in[4];
    const float* qco    = (const float*)d_in[5];
    const float* kco    = (const float*)d_in[6];
    const int*   qiso   = (const int*)d_in[7];
    const int*   kiso   = (const int*)d_in[8];
    const float* g1w    = (const float*)d_in[9];
    const float* g1b    = (const float*)d_in[10];
    const float* g2w    = (const float*)d_in[11];
    const float* g2b    = (const float*)d_in[12];
    const float* h1w    = (const float*)d_in[13];
    const float* h1b    = (const float*)d_in[14];
    const float* h2w    = (const float*)d_in[15];
    const float* h2b    = (const float*)d_in[16];
    const float* f1w    = (const float*)d_in[17];
    const float* f1b    = (const float*)d_in[18];
    const float* f2w    = (const float*)d_in[19];
    const float* f2b    = (const float*)d_in[20];
    const float* ln1g   = (const float*)d_in[21];
    const float* ln1b   = (const float*)d_in[22];
    const float* ln2g   = (const float*)d_in[23];
    const float* ln2b   = (const float*)d_in[24];
    float* out = (float*)d_out;

    float *pR, *pL, *pX, *pF1, *pP;
    cudaGetSymbolAddress((void**)&pR,  g_R);
    cudaGetSymbolAddress((void**)&pL,  g_L);
    cudaGetSymbolAddress((void**)&pX,  g_X);
    cudaGetSymbolAddress((void**)&pF1, g_F1);
    cudaGetSymbolAddress((void**)&pP,  g_P);

    // geometry chain
    reduce_k<<<dim3(RBLK, 2), 256>>>(qA, kA, qco, kco, qiso, kiso);
    reduce2_k<<<(2 * 15 * K_CL) / 256, 256>>>();
    cfeat_k<<<K_CL / 256, 256>>>(sensor, g1w, g1b, h1w, h1b);
    rfactor_k<<<dim3(16, 16), 256>>>(g2w, g2b, h2w, h2b, h1w);

    // logits = (Q @ K^T)/16 * R     (1024x1024x256)
    gemm_k2<128, 1, true><<<dim3(16, 8), 256>>>(query, keyemb, pL, K_CL, K_CL, DM, pR, 0.0625f);
    softmax_k<<<K_CL, 256>>>(pL);

    // attn @ key_emb  (1024x256x1024), split-K=2 -> partials
    gemm_s<<<dim3(4, 16, 2), 256>>>(pL, keyemb, pP, K_CL, DM, K_CL);
    // x = LN1(query + p0 + p1)
    add_ln3_k<false><<<K_CL, 256>>>(query, pP, pP + K_CL * DM, nullptr, ln1g, ln1b, pX);

    // FFN1: relu(x @ w1 + b1)   (1024x1024x256)
    gemm_k2<128, 2, false><<<dim3(16, 8), 256>>>(pX, f1w, pF1, K_CL, 4 * DM, DM, f1b, 1.f);

    // FFN2 partials (1024x256x1024), split-K=2
    gemm_s<<<dim3(4, 16, 2), 256>>>(pF1, f2w, pP, K_CL, DM, 4 * DM);
    // out = LN2(x + p0 + p1 + b2)
    add_ln3_k<true><<<K_CL, 256>>>(pX, pP, pP + K_CL * DM, f2b, ln2g, ln2b, out);
}